// round 12
// baseline (speedup 1.0000x reference)
#include <cuda_runtime.h>
#include <math.h>

#define NOISE_SCALE 0.1f
#define NOISE_RATIO 0.3f
#define ADAPTIVE_FACTOR 1.0f
#define MAX_NOISE 1.0f

#define B_ROWS 4096
#define D_COLS 4096
#define C_CLASSES 1000
#define C4 (C_CLASSES / 4)   // 250 float4 per model_output row
#define D4 (D_COLS / 4)      // 1024 float4 per data row

// Four blocks per row: each block redundantly computes the row's softmax
// confidence (sibling blocks' logits reads hit L2) and streams one QUARTER
// of the elementwise row (exactly 1 float4 of x/ru/ns per thread). Minimal
// register footprint -> ~8 CTAs/SM, matching the 82.8%-DRAM pure-streaming
// configuration, with the reduction latency hidden behind the loads.
__global__ __launch_bounds__(256) void fused_kernel(const float4* __restrict__ x,
                                                    const float4* __restrict__ mo4,
                                                    const float4* __restrict__ ru,
                                                    const float4* __restrict__ ns,
                                                    float4* __restrict__ out) {
    const int row = blockIdx.x >> 2;
    const int q   = blockIdx.x & 3;
    const int tid = threadIdx.x;
    const int lane = tid & 31;
    const int warp = tid >> 5;

    __shared__ float sm_m[8];   // per-warp max
    __shared__ float sm_s[8];   // per-warp sum of exp(l - m_w)

    // ---- 1) logits slice first (reduction depends only on this) ----
    float4 v;
    const bool have = (tid < C4);
    if (have) v = mo4[row * C4 + tid];
    else      v = make_float4(-INFINITY, -INFINITY, -INFINITY, -INFINITY);

    // ---- 2) this block's quarter-row: 3 LDG.128 in flight ----
    const int i = row * D4 + q * 256 + tid;   // fits in int
    float4 xv = __ldcs(&x[i]);
    float4 rv = __ldcs(&ru[i]);
    float4 nv = __ldcs(&ns[i]);

    // ---- 3) warp max tree, then sum-of-exp tree (overlaps load latency) ----
    float m = fmaxf(fmaxf(v.x, v.y), fmaxf(v.z, v.w));
    #pragma unroll
    for (int off = 16; off >= 1; off >>= 1)
        m = fmaxf(m, __shfl_xor_sync(0xffffffffu, m, off));  // warp max (uniform)

    float s = have ? (__expf(v.x - m) + __expf(v.y - m) +
                      __expf(v.z - m) + __expf(v.w - m))
                   : 0.0f;
    #pragma unroll
    for (int off = 16; off >= 1; off >>= 1)
        s += __shfl_xor_sync(0xffffffffu, s, off);

    if (lane == 0) { sm_m[warp] = m; sm_s[warp] = s; }
    __syncthreads();

    // ---- 4) every thread combines the 8 warp partials (no 2nd barrier) ----
    float M = sm_m[0];
    #pragma unroll
    for (int w = 1; w < 8; w++) M = fmaxf(M, sm_m[w]);
    float S = 0.0f;
    #pragma unroll
    for (int w = 0; w < 8; w++) S += sm_s[w] * __expf(sm_m[w] - M);
    const float conf = 1.0f / S;
    const float scale = fminf(NOISE_SCALE * (1.0f + ADAPTIVE_FACTOR * conf), MAX_NOISE);

    // ---- 5) apply + store ----
    float4 o;
    o.x = xv.x + (rv.x < NOISE_RATIO ? nv.x * scale : 0.0f);
    o.y = xv.y + (rv.y < NOISE_RATIO ? nv.y * scale : 0.0f);
    o.z = xv.z + (rv.z < NOISE_RATIO ? nv.z * scale : 0.0f);
    o.w = xv.w + (rv.w < NOISE_RATIO ? nv.w * scale : 0.0f);
    __stcs(&out[i], o);
}

extern "C" void kernel_launch(void* const* d_in, const int* in_sizes, int n_in,
                              void* d_out, int out_size) {
    const float* x  = (const float*)d_in[0];
    const float* mo = (const float*)d_in[1];
    const float* ru = (const float*)d_in[2];
    const float* ns = (const float*)d_in[3];
    float* out = (float*)d_out;

    fused_kernel<<<B_ROWS * 4, 256>>>((const float4*)x, (const float4*)mo,
                                      (const float4*)ru, (const float4*)ns,
                                      (float4*)out);
}

// round 13
// speedup vs baseline: 1.0054x; 1.0054x over previous
#include <cuda_runtime.h>
#include <math.h>

#define NOISE_SCALE 0.1f
#define NOISE_RATIO 0.3f
#define ADAPTIVE_FACTOR 1.0f
#define MAX_NOISE 1.0f

#define B_ROWS 4096
#define D_COLS 4096
#define C_CLASSES 1000
#define C4 (C_CLASSES / 4)   // 250 float4 per model_output row
#define D4 (D_COLS / 4)      // 1024 float4 per data row

// Two 512-thread blocks per row. Each thread: 1 float4 of x/ru/ns (3 loads
// front-batched) + logits slice for tid<250. Row softmax computed 2x per row
// (second read hits L2). Combine stage is hierarchical (warp partials ->
// warp-0 shuffle reduce -> smem broadcast) to keep issue work minimal.
__global__ __launch_bounds__(512) void fused_kernel(const float4* __restrict__ x,
                                                    const float4* __restrict__ mo4,
                                                    const float4* __restrict__ ru,
                                                    const float4* __restrict__ ns,
                                                    float4* __restrict__ out) {
    const int row  = blockIdx.x >> 1;
    const int half = blockIdx.x & 1;
    const int tid = threadIdx.x;
    const int lane = tid & 31;
    const int warp = tid >> 5;

    __shared__ float sm_m[16];  // per-warp max
    __shared__ float sm_s[16];  // per-warp sum of exp(l - m_w)
    __shared__ float s_scale;

    // ---- 1) logits slice first (reduction depends only on this) ----
    float4 v;
    const bool have = (tid < C4);
    if (have) v = mo4[row * C4 + tid];
    else      v = make_float4(-INFINITY, -INFINITY, -INFINITY, -INFINITY);

    // ---- 2) this block's half-row: 3 LDG.128 in flight per thread ----
    const int i = row * D4 + half * 512 + tid;   // fits in int
    float4 xv = __ldcs(&x[i]);
    float4 rv = __ldcs(&ru[i]);
    float4 nv = __ldcs(&ns[i]);

    // ---- 3) warp max tree, then sum-of-exp tree (overlaps load latency) ----
    float m = fmaxf(fmaxf(v.x, v.y), fmaxf(v.z, v.w));
    #pragma unroll
    for (int off = 16; off >= 1; off >>= 1)
        m = fmaxf(m, __shfl_xor_sync(0xffffffffu, m, off));  // warp max (uniform)

    float s = have ? (__expf(v.x - m) + __expf(v.y - m) +
                      __expf(v.z - m) + __expf(v.w - m))
                   : 0.0f;
    #pragma unroll
    for (int off = 16; off >= 1; off >>= 1)
        s += __shfl_xor_sync(0xffffffffu, s, off);

    if (lane == 0) { sm_m[warp] = m; sm_s[warp] = s; }
    __syncthreads();

    // ---- 4) warp 0 combines the 16 warp partials, broadcasts scale ----
    if (warp == 0) {
        const int w = lane & 15;
        float mw = sm_m[w];
        float sw = sm_s[w];
        float M = mw;
        #pragma unroll
        for (int off = 8; off >= 1; off >>= 1)
            M = fmaxf(M, __shfl_xor_sync(0xffffffffu, M, off));
        float part = sw * __expf(mw - M);
        // halves of the warp hold duplicate partial sets; reduce over 16 then
        // the duplicate halves agree, so a full 16-lane tree suffices.
        #pragma unroll
        for (int off = 8; off >= 1; off >>= 1)
            part += __shfl_xor_sync(0xffffffffu, part, off);
        // lanes 0-15 and 16-31 each summed their own copy of all 16 partials
        if (lane == 0) {
            float conf = 1.0f / part;
            s_scale = fminf(NOISE_SCALE * (1.0f + ADAPTIVE_FACTOR * conf), MAX_NOISE);
        }
    }
    __syncthreads();
    const float scale = s_scale;

    // ---- 5) apply + store ----
    float4 o;
    o.x = xv.x + (rv.x < NOISE_RATIO ? nv.x * scale : 0.0f);
    o.y = xv.y + (rv.y < NOISE_RATIO ? nv.y * scale : 0.0f);
    o.z = xv.z + (rv.z < NOISE_RATIO ? nv.z * scale : 0.0f);
    o.w = xv.w + (rv.w < NOISE_RATIO ? nv.w * scale : 0.0f);
    __stcs(&out[i], o);
}

extern "C" void kernel_launch(void* const* d_in, const int* in_sizes, int n_in,
                              void* d_out, int out_size) {
    const float* x  = (const float*)d_in[0];
    const float* mo = (const float*)d_in[1];
    const float* ru = (const float*)d_in[2];
    const float* ns = (const float*)d_in[3];
    float* out = (float*)d_out;

    fused_kernel<<<B_ROWS * 2, 512>>>((const float4*)x, (const float4*)mo,
                                      (const float4*)ru, (const float4*)ns,
                                      (float4*)out);
}

// round 14
// speedup vs baseline: 1.0585x; 1.0528x over previous
#include <cuda_runtime.h>
#include <math.h>

#define NOISE_SCALE 0.1f
#define NOISE_RATIO 0.3f
#define ADAPTIVE_FACTOR 1.0f
#define MAX_NOISE 1.0f

#define B_ROWS 4096
#define D_COLS 4096
#define C_CLASSES 1000
#define C4 (C_CLASSES / 4)   // 250 float4 per model_output row
#define D4 (D_COLS / 4)      // 1024 float4 per data row
#define NCHUNK (D4 / 256)    // 4 chunks of 256 float4 per row

// FINAL CHAMPION (R4 shape, validated twice: e2e 39.6/40.6, kernel 36.9/36.1).
// One block per row. Prefetch ALL elementwise loads into registers (13
// front-batched LDG.128 per thread), then do the softmax-confidence
// reduction (latency fully hidden behind the in-flight loads), then apply
// scale + streaming store. 272 MB compulsory traffic @ ~6.4 TB/s = at the
// measured HBM/LTS ceiling for this access pattern.
__global__ __launch_bounds__(256) void fused_kernel(const float4* __restrict__ x,
                                                    const float4* __restrict__ mo4,
                                                    const float4* __restrict__ ru,
                                                    const float4* __restrict__ ns,
                                                    float4* __restrict__ out) {
    const int row = blockIdx.x;
    const int tid = threadIdx.x;
    const int lane = tid & 31;
    const int warp = tid >> 5;

    __shared__ float sred[8];
    __shared__ float s_scale;

    // ---- 1) logits slice first (reduction depends only on this) ----
    float4 v;
    const bool have = (tid < C4);
    if (have) v = mo4[(long long)row * C4 + tid];
    else      v = make_float4(-INFINITY, -INFINITY, -INFINITY, -INFINITY);

    // ---- 2) prefetch all elementwise chunks (12 LDG.128 in flight) ----
    const long long base = (long long)row * D4;
    float4 xv[NCHUNK], rv[NCHUNK], nv[NCHUNK];
    #pragma unroll
    for (int j = 0; j < NCHUNK; j++) {
        const long long i = base + tid + j * 256;
        xv[j] = __ldcs(&x[i]);
        rv[j] = __ldcs(&ru[i]);
        nv[j] = __ldcs(&ns[i]);
    }

    // ---- 3) row max (waits only on v) ----
    float m = fmaxf(fmaxf(v.x, v.y), fmaxf(v.z, v.w));
    #pragma unroll
    for (int off = 16; off >= 1; off >>= 1)
        m = fmaxf(m, __shfl_xor_sync(0xffffffffu, m, off));
    if (lane == 0) sred[warp] = m;
    __syncthreads();
    if (warp == 0) {
        float mm = sred[lane & 7];
        #pragma unroll
        for (int off = 4; off >= 1; off >>= 1)
            mm = fmaxf(mm, __shfl_xor_sync(0xffffffffu, mm, off));
        if (lane == 0) sred[0] = mm;
    }
    __syncthreads();
    m = sred[0];

    // ---- 4) sum exp(l - m) ----
    float s = 0.0f;
    if (have)
        s = __expf(v.x - m) + __expf(v.y - m) + __expf(v.z - m) + __expf(v.w - m);
    #pragma unroll
    for (int off = 16; off >= 1; off >>= 1)
        s += __shfl_xor_sync(0xffffffffu, s, off);
    __syncthreads();
    if (lane == 0) sred[warp] = s;
    __syncthreads();
    if (warp == 0) {
        float ss = sred[lane & 7];
        #pragma unroll
        for (int off = 4; off >= 1; off >>= 1)
            ss += __shfl_xor_sync(0xffffffffu, ss, off);
        if (lane == 0) {
            float conf = 1.0f / ss;
            s_scale = fminf(NOISE_SCALE * (1.0f + ADAPTIVE_FACTOR * conf), MAX_NOISE);
        }
    }
    __syncthreads();
    const float scale = s_scale;

    // ---- 5) apply + store (data already resident in registers) ----
    #pragma unroll
    for (int j = 0; j < NCHUNK; j++) {
        const long long i = base + tid + j * 256;
        float4 o;
        o.x = xv[j].x + (rv[j].x < NOISE_RATIO ? nv[j].x * scale : 0.0f);
        o.y = xv[j].y + (rv[j].y < NOISE_RATIO ? nv[j].y * scale : 0.0f);
        o.z = xv[j].z + (rv[j].z < NOISE_RATIO ? nv[j].z * scale : 0.0f);
        o.w = xv[j].w + (rv[j].w < NOISE_RATIO ? nv[j].w * scale : 0.0f);
        __stcs(&out[i], o);
    }
}

extern "C" void kernel_launch(void* const* d_in, const int* in_sizes, int n_in,
                              void* d_out, int out_size) {
    const float* x  = (const float*)d_in[0];
    const float* mo = (const float*)d_in[1];
    const float* ru = (const float*)d_in[2];
    const float* ns = (const float*)d_in[3];
    float* out = (float*)d_out;

    fused_kernel<<<B_ROWS, 256>>>((const float4*)x, (const float4*)mo,
                                  (const float4*)ru, (const float4*)ns,
                                  (float4*)out);
}